// round 15
// baseline (speedup 1.0000x reference)
#include <cuda_runtime.h>

#define BATCH 8
#define NPTS  2048
#define KNN   20
#define ROWS  (BATCH*NPTS)
#define EPSBN 1e-5f
#define SLOPE 0.2f
#define TKCAP 256

static __device__ float g_x0[ROWS*3];
static __device__ float g_x1[ROWS*64];
static __device__ float g_x2[ROWS*64];
static __device__ float g_x3[ROWS*128];
static __device__ float g_x4[ROWS*256];
static __device__ float g_xx[ROWS];
static __device__ float g_D[(size_t)ROWS*NPTS];
static __device__ int   g_idx[ROWS*KNN];
static __device__ float g_A [ROWS*256];
static __device__ float g_Bm[ROWS*256];
static __device__ float g_h5[(size_t)ROWS*512];
static __device__ float g_S1[512];
static __device__ float g_S2[512];

// ---- packed fp32x2 helpers (sm_103a FFMA2 via PTX) --------------------------
__device__ __forceinline__ unsigned long long pk2(float lo, float hi){
    unsigned long long r;
    asm("mov.b64 %0, {%1,%2};" : "=l"(r) : "f"(lo), "f"(hi));
    return r;
}
__device__ __forceinline__ void upk2(unsigned long long v, float& lo, float& hi){
    asm("mov.b64 {%0,%1}, %2;" : "=f"(lo), "=f"(hi) : "l"(v));
}
__device__ __forceinline__ unsigned long long fma2(unsigned long long a,
                                                   unsigned long long b,
                                                   unsigned long long c){
    unsigned long long d;
    asm("fma.rn.f32x2 %0, %1, %2, %3;" : "=l"(d) : "l"(a), "l"(b), "l"(c));
    return d;
}

__global__ void k_trans0(const float* __restrict__ x){
    int t = blockIdx.x*256 + threadIdx.x;
    if (t >= ROWS) return;
    int b = t >> 11, n = t & 2047;
    float s = 0.f;
#pragma unroll
    for (int c=0;c<3;c++){
        float v = x[((size_t)(b*3+c))*NPTS + n];
        g_x0[t*3+c] = v; s += v*v;
    }
    g_xx[t] = s;
}

__global__ void k_zeroS(){ int t=threadIdx.x; g_S1[t]=0.f; g_S2[t]=0.f; }

// Symmetric distance GEMM (FFMA2 mainloop): upper-triangle tiles, both stores.
// Block (0,0) zeroes stats.
template<int C>
__global__ void __launch_bounds__(256,2) k_dist_sym(const float* __restrict__ X){
    __shared__ __align__(16) float As[8][128];
    __shared__ __align__(16) float Bs[8][128];
    __shared__ __align__(16) float Ts[64][132];
    int b = blockIdx.z;
    int t = blockIdx.x;
    int ti = 0;
    while (t >= 16 - ti){ t -= 16 - ti; ti++; }
    int tj = ti + t;
    int rowBase = ti*128, colBase = tj*128;
    const float* Xb = X + (size_t)b*NPTS*C;
    int tid = threadIdx.x, tr = tid>>4, tc = tid&15;
    int half = tid>>7, r = tid&127;
    int base = half ? colBase : rowBase;
    if (blockIdx.x==0 && blockIdx.z==0){ g_S1[tid]=0.f; g_S1[tid+256]=0.f;
                                         g_S2[tid]=0.f; g_S2[tid+256]=0.f; }

    unsigned long long acc2[8][4];
#pragma unroll
    for (int i=0;i<8;i++)
#pragma unroll
        for (int jp=0;jp<4;jp++) acc2[i][jp]=0ull;

    float vv[8];
    {
        if constexpr (C % 8 == 0){
            const float4* p = (const float4*)(Xb + (size_t)(base+r)*C);
            float4 v0=p[0], v1=p[1];
            vv[0]=v0.x;vv[1]=v0.y;vv[2]=v0.z;vv[3]=v0.w;
            vv[4]=v1.x;vv[5]=v1.y;vv[6]=v1.z;vv[7]=v1.w;
        } else {
#pragma unroll
            for (int c=0;c<8;c++) vv[c] = (c<C) ? Xb[(size_t)(base+r)*C+c] : 0.f;
        }
    }
    for (int kk=0; kk<C; kk+=8){
        float (*S)[128] = half ? Bs : As;
#pragma unroll
        for (int c=0;c<8;c++) S[c][r] = vv[c];
        __syncthreads();
        if (kk+8 < C){
            if constexpr (C % 8 == 0){
                const float4* p = (const float4*)(Xb + (size_t)(base+r)*C + kk+8);
                float4 v0=p[0], v1=p[1];
                vv[0]=v0.x;vv[1]=v0.y;vv[2]=v0.z;vv[3]=v0.w;
                vv[4]=v1.x;vv[5]=v1.y;vv[6]=v1.z;vv[7]=v1.w;
            } else {
#pragma unroll
                for (int c=0;c<8;c++) vv[c] = (kk+8+c<C) ? Xb[(size_t)(base+r)*C+kk+8+c] : 0.f;
            }
        }
#pragma unroll
        for (int k2=0;k2<8;k2++){
            float4 a0 = *(const float4*)&As[k2][tr*8];
            float4 a1 = *(const float4*)&As[k2][tr*8+4];
            float a[8]={a0.x,a0.y,a0.z,a0.w,a1.x,a1.y,a1.z,a1.w};
            unsigned long long bp[4];
#pragma unroll
            for (int jp=0;jp<4;jp++)
                bp[jp] = *(const unsigned long long*)&Bs[k2][tc*8 + 2*jp];
            unsigned long long ad[8];
#pragma unroll
            for (int i=0;i<8;i++) ad[i] = pk2(a[i], a[i]);
#pragma unroll
            for (int i=0;i<8;i++)
#pragma unroll
                for (int jp=0;jp<4;jp++)
                    acc2[i][jp] = fma2(ad[i], bp[jp], acc2[i][jp]);
        }
        __syncthreads();
    }

    float acc[8][8];
#pragma unroll
    for (int i=0;i<8;i++)
#pragma unroll
        for (int jp=0;jp<4;jp++) upk2(acc2[i][jp], acc[i][2*jp], acc[i][2*jp+1]);

    const float* xxb = g_xx + b*NPTS;
    float* Db = g_D + (size_t)b*NPTS*NPTS;
    {
        float xv[8];
#pragma unroll
        for (int j=0;j<8;j++) xv[j] = xxb[colBase + tc*8 + j];
#pragma unroll
        for (int i=0;i<8;i++){
            int rr = rowBase + tr*8 + i;
            float4 o0 = make_float4(xv[0]-2.f*acc[i][0], xv[1]-2.f*acc[i][1],
                                    xv[2]-2.f*acc[i][2], xv[3]-2.f*acc[i][3]);
            float4 o1 = make_float4(xv[4]-2.f*acc[i][4], xv[5]-2.f*acc[i][5],
                                    xv[6]-2.f*acc[i][6], xv[7]-2.f*acc[i][7]);
            *(float4*)&Db[(size_t)rr*NPTS + colBase + tc*8]     = o0;
            *(float4*)&Db[(size_t)rr*NPTS + colBase + tc*8 + 4] = o1;
        }
    }
    if (ti != tj){
        const float* xxr = xxb + rowBase;
#pragma unroll
        for (int ch=0; ch<2; ch++){
            __syncthreads();
            if ((tc>>3) == ch){
                int tcl = tc & 7;
#pragma unroll
                for (int i=0;i<8;i++)
#pragma unroll
                    for (int j=0;j<8;j++)
                        Ts[tcl*8+j][tr*8+i] = acc[i][j];
            }
            __syncthreads();
#pragma unroll
            for (int e=0;e<8;e++){
                int idx = tid + e*256;
                int cl = idx>>5, r4 = idx&31;
                int cc = colBase + ch*64 + cl;
                float4 tsv = *(const float4*)&Ts[cl][r4*4];
                float4 xv4 = *(const float4*)&xxr[r4*4];
                *(float4*)&Db[(size_t)cc*NPTS + rowBase + r4*4] =
                    make_float4(xv4.x-2.f*tsv.x, xv4.y-2.f*tsv.y,
                                xv4.z-2.f*tsv.z, xv4.w-2.f*tsv.w);
            }
        }
    }
}

__device__ __forceinline__ unsigned long long packdi(float f, int idx){
    unsigned u = __float_as_uint(f);
    u ^= (unsigned)(((int)u >> 31)) | 0x80000000u;
    return ((unsigned long long)u << 32) | (unsigned)idx;
}
__device__ __forceinline__ unsigned long long wmin64(unsigned long long v){
#pragma unroll
    for (int off=16; off; off>>=1){
        unsigned long long o = __shfl_xor_sync(0xffffffffu, v, off);
        if (o < v) v = o;
    }
    return v;
}
__device__ __forceinline__ float wminf(float v){
#pragma unroll
    for (int off=16; off; off>>=1)
        v = fminf(v, __shfl_xor_sync(0xffffffffu, v, off));
    return v;
}

// top-20 via group-min threshold select + exact compacted finish. 1 warp/row.
__global__ void __launch_bounds__(128) k_topk2(){
    __shared__ unsigned long long buf[4][TKCAP];
    int gw = (blockIdx.x*128 + threadIdx.x) >> 5;
    int lane = threadIdx.x & 31;
    int ws = (threadIdx.x >> 5);
    if (gw >= ROWS) return;
    const float* rowp = g_D + (size_t)gw*NPTS;

    float a = 3.4e38f, b = 3.4e38f;
#pragma unroll 4
    for (int t=0;t<16;t++){
        int m0 = t*128 + lane*4;
        float4 q = *(const float4*)(rowp + m0);
        float m = fminf(fminf(q.x,q.y), fminf(q.z,q.w));
        if (m < b){ if (m < a){ b=a; a=m; } else b=m; }
    }
    float T = 0.f;
#pragma unroll 1
    for (int e=0;e<20;e++){
        float mv = wminf(a);
        if (a == mv){ a = b; b = 3.4e38f; }
        T = mv;
    }
    int cnt = 0;
#pragma unroll 1
    for (int t=0;t<16;t++){
        int m0 = t*128 + lane*4;
        float4 q = *(const float4*)(rowp + m0);
        float vv[4]={q.x,q.y,q.z,q.w};
        float m = fminf(fminf(vv[0],vv[1]), fminf(vv[2],vv[3]));
        unsigned gb = __ballot_sync(0xffffffffu, m <= T);
        if (gb){
#pragma unroll
            for (int u=0;u<4;u++){
                bool hit = (vv[u] <= T);
                unsigned bal = __ballot_sync(0xffffffffu, hit);
                if (hit){
                    int pos = cnt + __popc(bal & ((1u<<lane)-1u));
                    if (pos < TKCAP) buf[ws][pos] = packdi(vv[u], m0+u);
                }
                cnt += __popc(bal);
            }
        }
    }
    int* outp = g_idx + (size_t)gw*KNN;
    if (cnt <= TKCAP){
        unsigned long long s[8];
#pragma unroll
        for (int q=0;q<8;q++){
            int sl = lane + 32*q;
            s[q] = (sl < cnt) ? buf[ws][sl] : ~0ull;
        }
#pragma unroll
        for (int i=0;i<8;i++)
#pragma unroll
            for (int j=0;j<7-i;j++)
                if (s[j+1] < s[j]){ unsigned long long tmp=s[j]; s[j]=s[j+1]; s[j+1]=tmp; }
#pragma unroll 1
        for (int e=0;e<KNN;e++){
            unsigned long long mv = wmin64(s[0]);
            if (s[0] == mv){
#pragma unroll
                for (int q=0;q<7;q++) s[q]=s[q+1];
                s[7]=~0ull;
            }
            if (lane==0) outp[e] = (int)(mv & 0xffffffffu);
        }
    } else {
        unsigned long long prev = 0;
        for (int e=0;e<KNN;e++){
            unsigned long long mn = ~0ull;
            for (int t=0;t<16;t++){
                int m0 = t*128 + lane*4;
                float4 q = *(const float4*)(rowp + m0);
                float vv[4]={q.x,q.y,q.z,q.w};
#pragma unroll
                for (int u=0;u<4;u++){
                    unsigned long long p = packdi(vv[u], m0+u);
                    if (p > prev && p < mn) mn = p;
                }
            }
            unsigned long long mv = wmin64(mn);
            prev = mv;
            if (lane==0) outp[e] = (int)(mv & 0xffffffffu);
        }
    }
}

// A = Wd.x ; Bm = (Wc-Wd).x   (64x64 tile)
template<int C,int O>
__global__ void __launch_bounds__(256) k_ab(const float* __restrict__ X, const float* __restrict__ W,
                                            float* __restrict__ Aout, float* __restrict__ Bout){
    __shared__ float Xs[8][64], Wds[8][64], Wms[8][64];
    int oBase = blockIdx.x*64, rowBase = blockIdx.y*64;
    int tid = threadIdx.x;
    int tr = tid>>4, tc = tid&15;
    float accA[4][4], accB[4][4];
#pragma unroll
    for (int i=0;i<4;i++)
#pragma unroll
        for (int j=0;j<4;j++){ accA[i][j]=0.f; accB[i][j]=0.f; }
    for (int kk=0; kk<C; kk+=8){
        for (int t=tid; t<3*512; t+=256){
            int tile=t>>9, idx=t&511, rr=idx&63, c=idx>>6;
            float val = 0.f;
            if (kk+c < C){
                if (tile==0)      val = X[(size_t)(rowBase+rr)*C + kk + c];
                else if (tile==1) val = W[(size_t)(oBase+rr)*(2*C) + kk + c];
                else              val = W[(size_t)(oBase+rr)*(2*C) + C + kk + c]
                                      - W[(size_t)(oBase+rr)*(2*C) + kk + c];
            }
            if (tile==0) Xs[c][rr]=val; else if (tile==1) Wds[c][rr]=val; else Wms[c][rr]=val;
        }
        __syncthreads();
#pragma unroll
        for (int k2=0;k2<8;k2++){
            float a[4],d[4],m[4];
#pragma unroll
            for (int i=0;i<4;i++) a[i]=Xs[k2][tr*4+i];
#pragma unroll
            for (int j=0;j<4;j++){ d[j]=Wds[k2][tc*4+j]; m[j]=Wms[k2][tc*4+j]; }
#pragma unroll
            for (int i=0;i<4;i++)
#pragma unroll
                for (int j=0;j<4;j++){ accA[i][j]+=a[i]*d[j]; accB[i][j]+=a[i]*m[j]; }
        }
        __syncthreads();
    }
#pragma unroll
    for (int i=0;i<4;i++){
        int row = rowBase + tr*4 + i;
#pragma unroll
        for (int j=0;j<4;j++){
            int o = oBase + tc*4 + j;
            Aout[(size_t)row*O + o] = accA[i][j];
            Bout[(size_t)row*O + o] = accB[i][j];
        }
    }
}

// gather + max over k + raw-h channel moments (scalar, proven).
template<int O>
__global__ void __launch_bounds__(256) k_gather(const float* __restrict__ A, const float* __restrict__ Bm,
                                                float* __restrict__ hout){
    __shared__ int sidx[16*KNN];
    __shared__ float sS1[O], sS2[O];
    int row0 = blockIdx.x*16;
    int tid = threadIdx.x;
    for (int l=tid; l<16*KNN; l+=256) sidx[l] = g_idx[row0*KNN + l];
    if (tid < O){ sS1[tid]=0.f; sS2[tid]=0.f; }
    __syncthreads();
    const int nsub = 256/O;
    int o = tid & (O-1);
    int sub = tid / O;
    int b = row0 >> 11;
    const float* Ab = A + (size_t)b*NPTS*O;
    float s1=0.f, s2=0.f;
    for (int p=sub; p<16; p+=nsub){
        int row = row0+p;
        float m = Bm[(size_t)row*O + o];
        float mx = -3.4e38f;
#pragma unroll
        for (int j=0;j<KNN;j++){
            float h = Ab[(size_t)sidx[p*KNN+j]*O + o] + m;
            mx = fmaxf(mx,h);
            s1 += h; s2 += h*h;
        }
        hout[(size_t)row*O + o] = mx;
    }
    atomicAdd(&sS1[o], s1);
    atomicAdd(&sS2[o], s2);
    __syncthreads();
    if (tid < O){ atomicAdd(&g_S1[tid], sS1[tid]); atomicAdd(&g_S2[tid], sS2[tid]); }
}

// fused BN-apply + leaky + next-layer row norms. 1 warp per row.
template<int O>
__global__ void __launch_bounds__(256) k_apply_norm(float* __restrict__ xio,
                                                    const float* __restrict__ gam,
                                                    const float* __restrict__ bet){
    int gw = blockIdx.x*8 + (threadIdx.x>>5);
    int lane = threadIdx.x & 31;
    const float ci = 1.f/(float)(ROWS*KNN);
    float* row = xio + (size_t)gw*O;
    float s = 0.f;
#pragma unroll
    for (int i=0;i<O/32;i++){
        int o = lane + 32*i;
        float mean = g_S1[o]*ci;
        float var  = g_S2[o]*ci - mean*mean;
        float sc = gam[o]*rsqrtf(var + EPSBN);
        float sh = bet[o] - mean*sc;
        float h = row[o]*sc + sh;
        h = h >= 0.f ? h : SLOPE*h;
        row[o] = h;
        s += h*h;
    }
#pragma unroll
    for (int off=16; off; off>>=1) s += __shfl_xor_sync(0xffffffffu, s, off);
    if (lane==0) g_xx[gw] = s;
}

// h5 = W5 . concat(x1..x4), FFMA2 mainloop, fused channel stats.
__global__ void __launch_bounds__(256,2) k_gemm5(const float* __restrict__ W5){
    __shared__ __align__(16) float As[8][128];
    __shared__ __align__(16) float Ws[8][128];
    __shared__ float sS1[128], sS2[128];
    int oBase = blockIdx.x*128, rowBase = blockIdx.y*128;
    int tid = threadIdx.x;
    if (tid < 128){ sS1[tid]=0.f; sS2[tid]=0.f; }
    int tr = tid>>4, tc = tid&15;
    unsigned long long acc2[8][4];
#pragma unroll
    for (int i=0;i<8;i++)
#pragma unroll
        for (int jp=0;jp<4;jp++) acc2[i][jp]=0ull;

    float4 pf0, pf1;
    auto ld5 = [&](int kk){
        if (tid < 128){
            const float* src; int cw, coff;
            if (kk < 64)     { src=g_x1; cw=64;  coff=kk;     }
            else if (kk<128) { src=g_x2; cw=64;  coff=kk-64;  }
            else if (kk<256) { src=g_x3; cw=128; coff=kk-128; }
            else             { src=g_x4; cw=256; coff=kk-256; }
            const float4* p = (const float4*)(src + (size_t)(rowBase+tid)*cw + coff);
            pf0=p[0]; pf1=p[1];
        } else {
            const float4* p = (const float4*)(W5 + (size_t)(oBase+tid-128)*512 + kk);
            pf0=p[0]; pf1=p[1];
        }
    };
    ld5(0);
    for (int kk=0; kk<512; kk+=8){
        if (tid < 128){
            int rr = tid;
            As[0][rr]=pf0.x;As[1][rr]=pf0.y;As[2][rr]=pf0.z;As[3][rr]=pf0.w;
            As[4][rr]=pf1.x;As[5][rr]=pf1.y;As[6][rr]=pf1.z;As[7][rr]=pf1.w;
        } else {
            int j = tid-128;
            Ws[0][j]=pf0.x;Ws[1][j]=pf0.y;Ws[2][j]=pf0.z;Ws[3][j]=pf0.w;
            Ws[4][j]=pf1.x;Ws[5][j]=pf1.y;Ws[6][j]=pf1.z;Ws[7][j]=pf1.w;
        }
        __syncthreads();
        if (kk+8 < 512) ld5(kk+8);
#pragma unroll
        for (int k2=0;k2<8;k2++){
            float4 a0 = *(const float4*)&As[k2][tr*8];
            float4 a1 = *(const float4*)&As[k2][tr*8+4];
            float a[8]={a0.x,a0.y,a0.z,a0.w,a1.x,a1.y,a1.z,a1.w};
            unsigned long long bp[4];
#pragma unroll
            for (int jp=0;jp<4;jp++)
                bp[jp] = *(const unsigned long long*)&Ws[k2][tc*8 + 2*jp];
            unsigned long long ad[8];
#pragma unroll
            for (int i=0;i<8;i++) ad[i] = pk2(a[i], a[i]);
#pragma unroll
            for (int i=0;i<8;i++)
#pragma unroll
                for (int jp=0;jp<4;jp++)
                    acc2[i][jp] = fma2(ad[i], bp[jp], acc2[i][jp]);
        }
        __syncthreads();
    }
    float acc[8][8];
#pragma unroll
    for (int i=0;i<8;i++)
#pragma unroll
        for (int jp=0;jp<4;jp++) upk2(acc2[i][jp], acc[i][2*jp], acc[i][2*jp+1]);

    float s1[8], s2[8];
#pragma unroll
    for (int j=0;j<8;j++){ s1[j]=0.f; s2[j]=0.f; }
#pragma unroll
    for (int i=0;i<8;i++){
        int rr = rowBase + tr*8 + i;
        float4 o0 = make_float4(acc[i][0],acc[i][1],acc[i][2],acc[i][3]);
        float4 o1 = make_float4(acc[i][4],acc[i][5],acc[i][6],acc[i][7]);
        *(float4*)&g_h5[(size_t)rr*512 + oBase + tc*8]     = o0;
        *(float4*)&g_h5[(size_t)rr*512 + oBase + tc*8 + 4] = o1;
#pragma unroll
        for (int j=0;j<8;j++){ float v = acc[i][j]; s1[j]+=v; s2[j]+=v*v; }
    }
#pragma unroll
    for (int j=0;j<8;j++){
        atomicAdd(&sS1[tc*8+j], s1[j]);
        atomicAdd(&sS2[tc*8+j], s2[j]);
    }
    __syncthreads();
    if (tid < 128){
        atomicAdd(&g_S1[oBase+tid], sS1[tid]);
        atomicAdd(&g_S2[oBase+tid], sS2[tid]);
    }
}

__global__ void k_pool(const float* __restrict__ gam, const float* __restrict__ bet,
                       float* __restrict__ out){
    int b = blockIdx.x, o = threadIdx.x;
    const float ci = 1.f/(float)ROWS;
    float mean = g_S1[o]*ci;
    float var  = g_S2[o]*ci - mean*mean;
    float sc = gam[o]*rsqrtf(var + EPSBN);
    float sh = bet[o] - mean*sc;
    float mx = -3.4e38f, sum = 0.f;
    const float* hb = g_h5 + (size_t)b*NPTS*512;
#pragma unroll 4
    for (int n=0;n<NPTS;n++){
        float h = hb[(size_t)n*512 + o]*sc + sh;
        h = h >= 0.f ? h : SLOPE*h;
        mx = fmaxf(mx,h); sum += h;
    }
    out[b*1024 + o]       = mx;
    out[b*1024 + 512 + o] = sum*(1.f/(float)NPTS);
}

extern "C" void kernel_launch(void* const* d_in, const int* in_sizes, int n_in,
                              void* d_out, int out_size){
    const float* x   = (const float*)d_in[0];
    const float* W1  = (const float*)d_in[2];
    const float* G1  = (const float*)d_in[3];
    const float* Bb1 = (const float*)d_in[4];
    const float* W2  = (const float*)d_in[5];
    const float* G2  = (const float*)d_in[6];
    const float* Bb2 = (const float*)d_in[7];
    const float* W3  = (const float*)d_in[8];
    const float* G3  = (const float*)d_in[9];
    const float* Bb3 = (const float*)d_in[10];
    const float* W4  = (const float*)d_in[11];
    const float* G4  = (const float*)d_in[12];
    const float* Bb4 = (const float*)d_in[13];
    const float* W5  = (const float*)d_in[14];
    const float* G5  = (const float*)d_in[15];
    const float* Bb5 = (const float*)d_in[16];
    float* out = (float*)d_out;

    float *px0,*px1,*px2,*px3,*px4,*pA,*pB;
    cudaGetSymbolAddress((void**)&px0, g_x0);
    cudaGetSymbolAddress((void**)&px1, g_x1);
    cudaGetSymbolAddress((void**)&px2, g_x2);
    cudaGetSymbolAddress((void**)&px3, g_x3);
    cudaGetSymbolAddress((void**)&px4, g_x4);
    cudaGetSymbolAddress((void**)&pA,  g_A);
    cudaGetSymbolAddress((void**)&pB,  g_Bm);

    dim3 gd(136, 1, BATCH);

    k_trans0<<<ROWS/256, 256>>>(x);

    // block 1: C=3 -> O=64   (4th launch = k_dist_sym<3>, for ncu)
    k_zeroS<<<1, 512>>>();
    k_ab<3,64><<<dim3(1, ROWS/64), 256>>>(px0, W1, pA, pB);
    k_dist_sym<3><<<gd, 256>>>(px0);
    k_topk2<<<ROWS/4, 128>>>();
    k_gather<64><<<ROWS/16, 256>>>(pA, pB, px1);
    k_apply_norm<64><<<ROWS/8, 256>>>(px1, G1, Bb1);

    // block 2: C=64 -> O=64
    k_dist_sym<64><<<gd, 256>>>(px1);
    k_ab<64,64><<<dim3(1, ROWS/64), 256>>>(px1, W2, pA, pB);
    k_topk2<<<ROWS/4, 128>>>();
    k_gather<64><<<ROWS/16, 256>>>(pA, pB, px2);
    k_apply_norm<64><<<ROWS/8, 256>>>(px2, G2, Bb2);

    // block 3: C=64 -> O=128
    k_dist_sym<64><<<gd, 256>>>(px2);
    k_ab<64,128><<<dim3(2, ROWS/64), 256>>>(px2, W3, pA, pB);
    k_topk2<<<ROWS/4, 128>>>();
    k_gather<128><<<ROWS/16, 256>>>(pA, pB, px3);
    k_apply_norm<128><<<ROWS/8, 256>>>(px3, G3, Bb3);

    // block 4: C=128 -> O=256
    k_dist_sym<128><<<gd, 256>>>(px3);
    k_ab<128,256><<<dim3(4, ROWS/64), 256>>>(px3, W4, pA, pB);
    k_topk2<<<ROWS/4, 128>>>();
    k_gather<256><<<ROWS/16, 256>>>(pA, pB, px4);
    k_apply_norm<256><<<ROWS/8, 256>>>(px4, G4, Bb4);

    // final
    k_zeroS<<<1, 512>>>();
    k_gemm5<<<dim3(4, ROWS/128), 256>>>(W5);
    k_pool<<<BATCH, 512>>>(G5, Bb5, out);
}

// round 16
// speedup vs baseline: 1.1319x; 1.1319x over previous
#include <cuda_runtime.h>

#define BATCH 8
#define NPTS  2048
#define KNN   20
#define ROWS  (BATCH*NPTS)
#define EPSBN 1e-5f
#define SLOPE 0.2f
#define TKCAP 256

static __device__ float g_x0[ROWS*3];
static __device__ float g_x1[ROWS*64];
static __device__ float g_x2[ROWS*64];
static __device__ float g_x3[ROWS*128];
static __device__ float g_x4[ROWS*256];
static __device__ float g_xx[ROWS];
static __device__ float g_D[(size_t)ROWS*NPTS];
static __device__ int   g_idx[ROWS*KNN];
static __device__ float g_A [ROWS*256];
static __device__ float g_Bm[ROWS*256];
static __device__ float g_h5[(size_t)ROWS*512];
static __device__ float g_S1[512];
static __device__ float g_S2[512];

__global__ void k_trans0(const float* __restrict__ x){
    int t = blockIdx.x*256 + threadIdx.x;
    if (t >= ROWS) return;
    int b = t >> 11, n = t & 2047;
    float s = 0.f;
#pragma unroll
    for (int c=0;c<3;c++){
        float v = x[((size_t)(b*3+c))*NPTS + n];
        g_x0[t*3+c] = v; s += v*v;
    }
    g_xx[t] = s;
}

__global__ void k_zeroS(){ int t=threadIdx.x; g_S1[t]=0.f; g_S2[t]=0.f; }

// Symmetric distance GEMM: upper-triangle tiles, both stores. Block (0,0) zeroes stats.
template<int C>
__global__ void __launch_bounds__(256,2) k_dist_sym(const float* __restrict__ X){
    __shared__ __align__(16) float As[8][128];
    __shared__ __align__(16) float Bs[8][128];
    __shared__ __align__(16) float Ts[64][132];
    int b = blockIdx.z;
    int t = blockIdx.x;
    int ti = 0;
    while (t >= 16 - ti){ t -= 16 - ti; ti++; }
    int tj = ti + t;
    int rowBase = ti*128, colBase = tj*128;
    const float* Xb = X + (size_t)b*NPTS*C;
    int tid = threadIdx.x, tr = tid>>4, tc = tid&15;
    int half = tid>>7, r = tid&127;
    int base = half ? colBase : rowBase;
    if (blockIdx.x==0 && blockIdx.z==0){ g_S1[tid]=0.f; g_S1[tid+256]=0.f;
                                         g_S2[tid]=0.f; g_S2[tid+256]=0.f; }

    float acc[8][8];
#pragma unroll
    for (int i=0;i<8;i++)
#pragma unroll
        for (int j=0;j<8;j++) acc[i][j]=0.f;

    float vv[8];
    {
        if constexpr (C % 8 == 0){
            const float4* p = (const float4*)(Xb + (size_t)(base+r)*C);
            float4 v0=p[0], v1=p[1];
            vv[0]=v0.x;vv[1]=v0.y;vv[2]=v0.z;vv[3]=v0.w;
            vv[4]=v1.x;vv[5]=v1.y;vv[6]=v1.z;vv[7]=v1.w;
        } else {
#pragma unroll
            for (int c=0;c<8;c++) vv[c] = (c<C) ? Xb[(size_t)(base+r)*C+c] : 0.f;
        }
    }
    for (int kk=0; kk<C; kk+=8){
        float (*S)[128] = half ? Bs : As;
#pragma unroll
        for (int c=0;c<8;c++) S[c][r] = vv[c];
        __syncthreads();
        if (kk+8 < C){
            if constexpr (C % 8 == 0){
                const float4* p = (const float4*)(Xb + (size_t)(base+r)*C + kk+8);
                float4 v0=p[0], v1=p[1];
                vv[0]=v0.x;vv[1]=v0.y;vv[2]=v0.z;vv[3]=v0.w;
                vv[4]=v1.x;vv[5]=v1.y;vv[6]=v1.z;vv[7]=v1.w;
            } else {
#pragma unroll
                for (int c=0;c<8;c++) vv[c] = (kk+8+c<C) ? Xb[(size_t)(base+r)*C+kk+8+c] : 0.f;
            }
        }
#pragma unroll
        for (int k2=0;k2<8;k2++){
            float4 a0 = *(const float4*)&As[k2][tr*8];
            float4 a1 = *(const float4*)&As[k2][tr*8+4];
            float4 b0 = *(const float4*)&Bs[k2][tc*8];
            float4 b1 = *(const float4*)&Bs[k2][tc*8+4];
            float a[8]={a0.x,a0.y,a0.z,a0.w,a1.x,a1.y,a1.z,a1.w};
            float bb[8]={b0.x,b0.y,b0.z,b0.w,b1.x,b1.y,b1.z,b1.w};
#pragma unroll
            for (int i=0;i<8;i++)
#pragma unroll
                for (int j=0;j<8;j++) acc[i][j] += a[i]*bb[j];
        }
        __syncthreads();
    }

    const float* xxb = g_xx + b*NPTS;
    float* Db = g_D + (size_t)b*NPTS*NPTS;
    {
        float xv[8];
#pragma unroll
        for (int j=0;j<8;j++) xv[j] = xxb[colBase + tc*8 + j];
#pragma unroll
        for (int i=0;i<8;i++){
            int rr = rowBase + tr*8 + i;
            float4 o0 = make_float4(xv[0]-2.f*acc[i][0], xv[1]-2.f*acc[i][1],
                                    xv[2]-2.f*acc[i][2], xv[3]-2.f*acc[i][3]);
            float4 o1 = make_float4(xv[4]-2.f*acc[i][4], xv[5]-2.f*acc[i][5],
                                    xv[6]-2.f*acc[i][6], xv[7]-2.f*acc[i][7]);
            *(float4*)&Db[(size_t)rr*NPTS + colBase + tc*8]     = o0;
            *(float4*)&Db[(size_t)rr*NPTS + colBase + tc*8 + 4] = o1;
        }
    }
    if (ti != tj){
        const float* xxr = xxb + rowBase;
#pragma unroll
        for (int ch=0; ch<2; ch++){
            __syncthreads();
            if ((tc>>3) == ch){
                int tcl = tc & 7;
#pragma unroll
                for (int i=0;i<8;i++)
#pragma unroll
                    for (int j=0;j<8;j++)
                        Ts[tcl*8+j][tr*8+i] = acc[i][j];
            }
            __syncthreads();
#pragma unroll
            for (int e=0;e<8;e++){
                int idx = tid + e*256;
                int cl = idx>>5, r4 = idx&31;
                int cc = colBase + ch*64 + cl;
                float4 tsv = *(const float4*)&Ts[cl][r4*4];
                float4 xv4 = *(const float4*)&xxr[r4*4];
                *(float4*)&Db[(size_t)cc*NPTS + rowBase + r4*4] =
                    make_float4(xv4.x-2.f*tsv.x, xv4.y-2.f*tsv.y,
                                xv4.z-2.f*tsv.z, xv4.w-2.f*tsv.w);
            }
        }
    }
}

__device__ __forceinline__ unsigned long long packdi(float f, int idx){
    unsigned u = __float_as_uint(f);
    u ^= (unsigned)(((int)u >> 31)) | 0x80000000u;
    return ((unsigned long long)u << 32) | (unsigned)idx;
}
__device__ __forceinline__ unsigned long long wmin64(unsigned long long v){
#pragma unroll
    for (int off=16; off; off>>=1){
        unsigned long long o = __shfl_xor_sync(0xffffffffu, v, off);
        if (o < v) v = o;
    }
    return v;
}
__device__ __forceinline__ float wminf(float v){
#pragma unroll
    for (int off=16; off; off>>=1)
        v = fminf(v, __shfl_xor_sync(0xffffffffu, v, off));
    return v;
}

// top-20 via group-min threshold select + exact compacted finish. 1 warp/row.
__global__ void __launch_bounds__(128) k_topk2(){
    __shared__ unsigned long long buf[4][TKCAP];
    int gw = (blockIdx.x*128 + threadIdx.x) >> 5;
    int lane = threadIdx.x & 31;
    int ws = (threadIdx.x >> 5);
    if (gw >= ROWS) return;
    const float* rowp = g_D + (size_t)gw*NPTS;

    float a = 3.4e38f, b = 3.4e38f;
#pragma unroll 4
    for (int t=0;t<16;t++){
        int m0 = t*128 + lane*4;
        float4 q = *(const float4*)(rowp + m0);
        float m = fminf(fminf(q.x,q.y), fminf(q.z,q.w));
        if (m < b){ if (m < a){ b=a; a=m; } else b=m; }
    }
    float T = 0.f;
#pragma unroll 1
    for (int e=0;e<20;e++){
        float mv = wminf(a);
        if (a == mv){ a = b; b = 3.4e38f; }
        T = mv;
    }
    int cnt = 0;
#pragma unroll 1
    for (int t=0;t<16;t++){
        int m0 = t*128 + lane*4;
        float4 q = *(const float4*)(rowp + m0);
        float vv[4]={q.x,q.y,q.z,q.w};
        float m = fminf(fminf(vv[0],vv[1]), fminf(vv[2],vv[3]));
        unsigned gb = __ballot_sync(0xffffffffu, m <= T);
        if (gb){
#pragma unroll
            for (int u=0;u<4;u++){
                bool hit = (vv[u] <= T);
                unsigned bal = __ballot_sync(0xffffffffu, hit);
                if (hit){
                    int pos = cnt + __popc(bal & ((1u<<lane)-1u));
                    if (pos < TKCAP) buf[ws][pos] = packdi(vv[u], m0+u);
                }
                cnt += __popc(bal);
            }
        }
    }
    int* outp = g_idx + (size_t)gw*KNN;
    if (cnt <= TKCAP){
        unsigned long long s[8];
#pragma unroll
        for (int q=0;q<8;q++){
            int sl = lane + 32*q;
            s[q] = (sl < cnt) ? buf[ws][sl] : ~0ull;
        }
#pragma unroll
        for (int i=0;i<8;i++)
#pragma unroll
            for (int j=0;j<7-i;j++)
                if (s[j+1] < s[j]){ unsigned long long tmp=s[j]; s[j]=s[j+1]; s[j+1]=tmp; }
#pragma unroll 1
        for (int e=0;e<KNN;e++){
            unsigned long long mv = wmin64(s[0]);
            if (s[0] == mv){
#pragma unroll
                for (int q=0;q<7;q++) s[q]=s[q+1];
                s[7]=~0ull;
            }
            if (lane==0) outp[e] = (int)(mv & 0xffffffffu);
        }
    } else {
        unsigned long long prev = 0;
        for (int e=0;e<KNN;e++){
            unsigned long long mn = ~0ull;
            for (int t=0;t<16;t++){
                int m0 = t*128 + lane*4;
                float4 q = *(const float4*)(rowp + m0);
                float vv[4]={q.x,q.y,q.z,q.w};
#pragma unroll
                for (int u=0;u<4;u++){
                    unsigned long long p = packdi(vv[u], m0+u);
                    if (p > prev && p < mn) mn = p;
                }
            }
            unsigned long long mv = wmin64(mn);
            prev = mv;
            if (lane==0) outp[e] = (int)(mv & 0xffffffffu);
        }
    }
}

// A = Wd.x ; Bm = (Wc-Wd).x   (64x64 tile)
template<int C,int O>
__global__ void __launch_bounds__(256) k_ab(const float* __restrict__ X, const float* __restrict__ W,
                                            float* __restrict__ Aout, float* __restrict__ Bout){
    __shared__ float Xs[8][64], Wds[8][64], Wms[8][64];
    int oBase = blockIdx.x*64, rowBase = blockIdx.y*64;
    int tid = threadIdx.x;
    int tr = tid>>4, tc = tid&15;
    float accA[4][4], accB[4][4];
#pragma unroll
    for (int i=0;i<4;i++)
#pragma unroll
        for (int j=0;j<4;j++){ accA[i][j]=0.f; accB[i][j]=0.f; }
    for (int kk=0; kk<C; kk+=8){
        for (int t=tid; t<3*512; t+=256){
            int tile=t>>9, idx=t&511, rr=idx&63, c=idx>>6;
            float val = 0.f;
            if (kk+c < C){
                if (tile==0)      val = X[(size_t)(rowBase+rr)*C + kk + c];
                else if (tile==1) val = W[(size_t)(oBase+rr)*(2*C) + kk + c];
                else              val = W[(size_t)(oBase+rr)*(2*C) + C + kk + c]
                                      - W[(size_t)(oBase+rr)*(2*C) + kk + c];
            }
            if (tile==0) Xs[c][rr]=val; else if (tile==1) Wds[c][rr]=val; else Wms[c][rr]=val;
        }
        __syncthreads();
#pragma unroll
        for (int k2=0;k2<8;k2++){
            float a[4],d[4],m[4];
#pragma unroll
            for (int i=0;i<4;i++) a[i]=Xs[k2][tr*4+i];
#pragma unroll
            for (int j=0;j<4;j++){ d[j]=Wds[k2][tc*4+j]; m[j]=Wms[k2][tc*4+j]; }
#pragma unroll
            for (int i=0;i<4;i++)
#pragma unroll
                for (int j=0;j<4;j++){ accA[i][j]+=a[i]*d[j]; accB[i][j]+=a[i]*m[j]; }
        }
        __syncthreads();
    }
#pragma unroll
    for (int i=0;i<4;i++){
        int row = rowBase + tr*4 + i;
#pragma unroll
        for (int j=0;j<4;j++){
            int o = oBase + tc*4 + j;
            Aout[(size_t)row*O + o] = accA[i][j];
            Bout[(size_t)row*O + o] = accB[i][j];
        }
    }
}

// gather + max over k + raw-h channel moments (scalar, proven).
template<int O>
__global__ void __launch_bounds__(256) k_gather(const float* __restrict__ A, const float* __restrict__ Bm,
                                                float* __restrict__ hout){
    __shared__ int sidx[16*KNN];
    __shared__ float sS1[O], sS2[O];
    int row0 = blockIdx.x*16;
    int tid = threadIdx.x;
    for (int l=tid; l<16*KNN; l+=256) sidx[l] = g_idx[row0*KNN + l];
    if (tid < O){ sS1[tid]=0.f; sS2[tid]=0.f; }
    __syncthreads();
    const int nsub = 256/O;
    int o = tid & (O-1);
    int sub = tid / O;
    int b = row0 >> 11;
    const float* Ab = A + (size_t)b*NPTS*O;
    float s1=0.f, s2=0.f;
    for (int p=sub; p<16; p+=nsub){
        int row = row0+p;
        float m = Bm[(size_t)row*O + o];
        float mx = -3.4e38f;
#pragma unroll
        for (int j=0;j<KNN;j++){
            float h = Ab[(size_t)sidx[p*KNN+j]*O + o] + m;
            mx = fmaxf(mx,h);
            s1 += h; s2 += h*h;
        }
        hout[(size_t)row*O + o] = mx;
    }
    atomicAdd(&sS1[o], s1);
    atomicAdd(&sS2[o], s2);
    __syncthreads();
    if (tid < O){ atomicAdd(&g_S1[tid], sS1[tid]); atomicAdd(&g_S2[tid], sS2[tid]); }
}

// fused BN-apply + leaky + next-layer row norms. 1 warp per row.
template<int O>
__global__ void __launch_bounds__(256) k_apply_norm(float* __restrict__ xio,
                                                    const float* __restrict__ gam,
                                                    const float* __restrict__ bet){
    int gw = blockIdx.x*8 + (threadIdx.x>>5);
    int lane = threadIdx.x & 31;
    const float ci = 1.f/(float)(ROWS*KNN);
    float* row = xio + (size_t)gw*O;
    float s = 0.f;
#pragma unroll
    for (int i=0;i<O/32;i++){
        int o = lane + 32*i;
        float mean = g_S1[o]*ci;
        float var  = g_S2[o]*ci - mean*mean;
        float sc = gam[o]*rsqrtf(var + EPSBN);
        float sh = bet[o] - mean*sc;
        float h = row[o]*sc + sh;
        h = h >= 0.f ? h : SLOPE*h;
        row[o] = h;
        s += h*h;
    }
#pragma unroll
    for (int off=16; off; off>>=1) s += __shfl_xor_sync(0xffffffffu, s, off);
    if (lane==0) g_xx[gw] = s;
}

// h5 = W5 . concat(x1..x4) with fused channel stats. Stats zeroed before.
__global__ void __launch_bounds__(256,2) k_gemm5(const float* __restrict__ W5){
    __shared__ __align__(16) float As[8][128];
    __shared__ __align__(16) float Ws[8][128];
    __shared__ float sS1[128], sS2[128];
    int oBase = blockIdx.x*128, rowBase = blockIdx.y*128;
    int tid = threadIdx.x;
    if (tid < 128){ sS1[tid]=0.f; sS2[tid]=0.f; }
    int tr = tid>>4, tc = tid&15;
    float acc[8][8];
#pragma unroll
    for (int i=0;i<8;i++)
#pragma unroll
        for (int j=0;j<8;j++) acc[i][j]=0.f;

    float4 pf0, pf1;
    auto ld5 = [&](int kk){
        if (tid < 128){
            const float* src; int cw, coff;
            if (kk < 64)     { src=g_x1; cw=64;  coff=kk;     }
            else if (kk<128) { src=g_x2; cw=64;  coff=kk-64;  }
            else if (kk<256) { src=g_x3; cw=128; coff=kk-128; }
            else             { src=g_x4; cw=256; coff=kk-256; }
            const float4* p = (const float4*)(src + (size_t)(rowBase+tid)*cw + coff);
            pf0=p[0]; pf1=p[1];
        } else {
            const float4* p = (const float4*)(W5 + (size_t)(oBase+tid-128)*512 + kk);
            pf0=p[0]; pf1=p[1];
        }
    };
    ld5(0);
    for (int kk=0; kk<512; kk+=8){
        if (tid < 128){
            int rr = tid;
            As[0][rr]=pf0.x;As[1][rr]=pf0.y;As[2][rr]=pf0.z;As[3][rr]=pf0.w;
            As[4][rr]=pf1.x;As[5][rr]=pf1.y;As[6][rr]=pf1.z;As[7][rr]=pf1.w;
        } else {
            int j = tid-128;
            Ws[0][j]=pf0.x;Ws[1][j]=pf0.y;Ws[2][j]=pf0.z;Ws[3][j]=pf0.w;
            Ws[4][j]=pf1.x;Ws[5][j]=pf1.y;Ws[6][j]=pf1.z;Ws[7][j]=pf1.w;
        }
        __syncthreads();
        if (kk+8 < 512) ld5(kk+8);
#pragma unroll
        for (int k2=0;k2<8;k2++){
            float4 a0 = *(const float4*)&As[k2][tr*8];
            float4 a1 = *(const float4*)&As[k2][tr*8+4];
            float4 b0 = *(const float4*)&Ws[k2][tc*8];
            float4 b1 = *(const float4*)&Ws[k2][tc*8+4];
            float a[8]={a0.x,a0.y,a0.z,a0.w,a1.x,a1.y,a1.z,a1.w};
            float bb[8]={b0.x,b0.y,b0.z,b0.w,b1.x,b1.y,b1.z,b1.w};
#pragma unroll
            for (int i=0;i<8;i++)
#pragma unroll
                for (int j=0;j<8;j++) acc[i][j] += a[i]*bb[j];
        }
        __syncthreads();
    }
    float s1[8], s2[8];
#pragma unroll
    for (int j=0;j<8;j++){ s1[j]=0.f; s2[j]=0.f; }
#pragma unroll
    for (int i=0;i<8;i++){
        int rr = rowBase + tr*8 + i;
        float4 o0 = make_float4(acc[i][0],acc[i][1],acc[i][2],acc[i][3]);
        float4 o1 = make_float4(acc[i][4],acc[i][5],acc[i][6],acc[i][7]);
        *(float4*)&g_h5[(size_t)rr*512 + oBase + tc*8]     = o0;
        *(float4*)&g_h5[(size_t)rr*512 + oBase + tc*8 + 4] = o1;
#pragma unroll
        for (int j=0;j<8;j++){ float v = acc[i][j]; s1[j]+=v; s2[j]+=v*v; }
    }
#pragma unroll
    for (int j=0;j<8;j++){
        atomicAdd(&sS1[tc*8+j], s1[j]);
        atomicAdd(&sS2[tc*8+j], s2[j]);
    }
    __syncthreads();
    if (tid < 128){
        atomicAdd(&g_S1[oBase+tid], sS1[tid]);
        atomicAdd(&g_S2[oBase+tid], sS2[tid]);
    }
}

// two-stage final pool: partials over 256-point chunks, then reduce.
__global__ void k_pool_part(float* __restrict__ scratch){
    int chunk = blockIdx.x, b = blockIdx.y, o = threadIdx.x;
    const float ci = 1.f/(float)ROWS;
    float mean = g_S1[o]*ci;
    float var  = g_S2[o]*ci - mean*mean;
    float sc = __ldg(&g_S1[o])*0.f + mean*0.f + 0.f; // placeholder no-op avoided below
    sc = rsqrtf(var + EPSBN);
    // note: gamma/beta applied in final stage would break max; apply here:
    // we pass gamma/beta via scratch? simpler: recompute in both stages with same params.
    // This kernel applies raw-normalization only if gamma/beta were identity; instead we
    // fold gamma/beta in k_pool_fin? Max doesn't commute with affine unless applied first.
    // So gamma/beta must be applied HERE. They are passed via kernel args in launch below.
    (void)sc;
    scratch[0] = scratch[0]; // dead
}

// real partial kernel (gamma/beta passed explicitly)
__global__ void k_pool_part2(const float* __restrict__ gam, const float* __restrict__ bet,
                             float* __restrict__ pmax, float* __restrict__ psum){
    int chunk = blockIdx.x, b = blockIdx.y, o = threadIdx.x;
    const float ci = 1.f/(float)ROWS;
    float mean = g_S1[o]*ci;
    float var  = g_S2[o]*ci - mean*mean;
    float sc = gam[o]*rsqrtf(var + EPSBN);
    float sh = bet[o] - mean*sc;
    float mx = -3.4e38f, sum = 0.f;
    const float* hb = g_h5 + (size_t)b*NPTS*512 + (size_t)chunk*256*512;
#pragma unroll 4
    for (int n=0;n<256;n++){
        float h = hb[(size_t)n*512 + o]*sc + sh;
        h = h >= 0.f ? h : SLOPE*h;
        mx = fmaxf(mx,h); sum += h;
    }
    pmax[(b*8+chunk)*512 + o] = mx;
    psum[(b*8+chunk)*512 + o] = sum;
}

__global__ void k_pool_fin(const float* __restrict__ pmax, const float* __restrict__ psum,
                           float* __restrict__ out){
    int b = blockIdx.x, o = threadIdx.x;
    float mx = -3.4e38f, sum = 0.f;
#pragma unroll
    for (int c=0;c<8;c++){
        mx = fmaxf(mx, pmax[(b*8+c)*512 + o]);
        sum += psum[(b*8+c)*512 + o];
    }
    out[b*1024 + o]       = mx;
    out[b*1024 + 512 + o] = sum*(1.f/(float)NPTS);
}

extern "C" void kernel_launch(void* const* d_in, const int* in_sizes, int n_in,
                              void* d_out, int out_size){
    const float* x   = (const float*)d_in[0];
    const float* W1  = (const float*)d_in[2];
    const float* G1  = (const float*)d_in[3];
    const float* Bb1 = (const float*)d_in[4];
    const float* W2  = (const float*)d_in[5];
    const float* G2  = (const float*)d_in[6];
    const float* Bb2 = (const float*)d_in[7];
    const float* W3  = (const float*)d_in[8];
    const float* G3  = (const float*)d_in[9];
    const float* Bb3 = (const float*)d_in[10];
    const float* W4  = (const float*)d_in[11];
    const float* G4  = (const float*)d_in[12];
    const float* Bb4 = (const float*)d_in[13];
    const float* W5  = (const float*)d_in[14];
    const float* G5  = (const float*)d_in[15];
    const float* Bb5 = (const float*)d_in[16];
    float* out = (float*)d_out;

    float *px0,*px1,*px2,*px3,*px4,*pA,*pB;
    cudaGetSymbolAddress((void**)&px0, g_x0);
    cudaGetSymbolAddress((void**)&px1, g_x1);
    cudaGetSymbolAddress((void**)&px2, g_x2);
    cudaGetSymbolAddress((void**)&px3, g_x3);
    cudaGetSymbolAddress((void**)&px4, g_x4);
    cudaGetSymbolAddress((void**)&pA,  g_A);
    cudaGetSymbolAddress((void**)&pB,  g_Bm);

    dim3 gd(136, 1, BATCH);

    k_trans0<<<ROWS/256, 256>>>(x);

    // block 1: C=3 -> O=64   (4th launch = k_topk2, for ncu)
    k_ab<3,64><<<dim3(1, ROWS/64), 256>>>(px0, W1, pA, pB);
    k_dist_sym<3><<<gd, 256>>>(px0);
    k_topk2<<<ROWS/4, 128>>>();
    k_gather<64><<<ROWS/16, 256>>>(pA, pB, px1);
    k_apply_norm<64><<<ROWS/8, 256>>>(px1, G1, Bb1);

    // block 2: C=64 -> O=64
    k_dist_sym<64><<<gd, 256>>>(px1);
    k_ab<64,64><<<dim3(1, ROWS/64), 256>>>(px1, W2, pA, pB);
    k_topk2<<<ROWS/4, 128>>>();
    k_gather<64><<<ROWS/16, 256>>>(pA, pB, px2);
    k_apply_norm<64><<<ROWS/8, 256>>>(px2, G2, Bb2);

    // block 3: C=64 -> O=128
    k_dist_sym<64><<<gd, 256>>>(px2);
    k_ab<64,128><<<dim3(2, ROWS/64), 256>>>(px2, W3, pA, pB);
    k_topk2<<<ROWS/4, 128>>>();
    k_gather<128><<<ROWS/16, 256>>>(pA, pB, px3);
    k_apply_norm<128><<<ROWS/8, 256>>>(px3, G3, Bb3);

    // block 4: C=128 -> O=256
    k_dist_sym<128><<<gd, 256>>>(px3);
    k_ab<128,256><<<dim3(4, ROWS/64), 256>>>(px3, W4, pA, pB);
    k_topk2<<<ROWS/4, 128>>>();
    k_gather<256><<<ROWS/16, 256>>>(pA, pB, px4);
    k_apply_norm<256><<<ROWS/8, 256>>>(px4, G4, Bb4);

    // final
    k_zeroS<<<1, 512>>>();
    k_gemm5<<<dim3(4, ROWS/128), 256>>>(W5);
    k_pool_part2<<<dim3(8, BATCH), 512>>>(G5, Bb5, pA, pB);  // scratch reuse
    k_pool_fin<<<BATCH, 512>>>(pA, pB, out);
}